// round 14
// baseline (speedup 1.0000x reference)
#include <cuda_runtime.h>
#include <cstdint>
#include <cuda_fp16.h>

// Problem constants (fixed by the reference).
constexpr int Bn = 2;
constexpr int Np = 20000;
constexpr int R  = Bn * Np;       // 40000 point rows

// Scratch (allocation-free rule: __device__ globals).
__device__ __half g_h0h [R * 64];    // leaky(inp @ W_init^T + b)      [R,64]
__device__ __half g_x1h [R * 128];   // [t1_mean | fn1_mean]           [R,128]
__device__ __half g_t2mh[R * 128];   // mean_k leaky(geom @ Wl2^T + b) [R,128]
__device__ __half g_x2h [R * 256];   // [t2_mean | fn2_mean]           [R,256]
__device__ __half g_Wfh [256 * 256]; // fp16 W_fin
__device__ __half g_Wdh [256 * 256]; // fp16 W_id
__device__ __half g_Wih [64 * 256];  // fp16 W_init

__device__ __forceinline__ float leaky(float x) { return x > 0.f ? x : 0.1f * x; }

__device__ __forceinline__ uint32_t pack2(float a, float b) {
    __half2 h = __floats2half2_rn(a, b);
    return *reinterpret_cast<uint32_t*>(&h);
}
// m16n8k16 row.col f32 <- f16*f16 + f32 (base ISA, sm_80+).
__device__ __forceinline__ void mma_fp16(float* c, const uint32_t* a, const uint32_t* b) {
    asm volatile(
        "mma.sync.aligned.m16n8k16.row.col.f32.f16.f16.f32 "
        "{%0,%1,%2,%3},{%4,%5,%6,%7},{%8,%9},{%0,%1,%2,%3};"
        : "+f"(c[0]), "+f"(c[1]), "+f"(c[2]), "+f"(c[3])
        : "r"(a[0]), "r"(a[1]), "r"(a[2]), "r"(a[3]), "r"(b[0]), "r"(b[1]));
}
// ldmatrix x4 (base ISA, sm_75+).
__device__ __forceinline__ void ldsm4(uint32_t* r, uint32_t addr) {
    asm volatile("ldmatrix.sync.aligned.m8n8.x4.shared.b16 {%0,%1,%2,%3}, [%4];"
                 : "=r"(r[0]), "=r"(r[1]), "=r"(r[2]), "=r"(r[3]) : "r"(addr));
}

// Packed fp32x2 FMA (PTX ISA sm_100+, base target).
typedef unsigned long long u64;
__device__ __forceinline__ u64 pk2(float x, float y) {
    u64 r; asm("mov.b64 %0, {%1, %2};" : "=l"(r) : "f"(x), "f"(y)); return r;
}
__device__ __forceinline__ void upk2(u64 v, float& x, float& y) {
    asm("mov.b64 {%0, %1}, %2;" : "=f"(x), "=f"(y) : "l"(v));
}
__device__ __forceinline__ u64 fma2_(u64 a, u64 b, u64 c) {
    u64 d; asm("fma.rn.f32x2 %0, %1, %2, %3;" : "=l"(d) : "l"(a), "l"(b), "l"(c));
    return d;
}

// ---------------------------------------------------------------------------
// k_cvtw: one-shot fp32 -> fp16 conversion of the three GEMM weight matrices.
// ---------------------------------------------------------------------------
__global__ __launch_bounds__(256) void k_cvtw(const float* __restrict__ Wf,
                                              const float* __restrict__ Wd,
                                              const float* __restrict__ Wi) {
    int i = blockIdx.x * 256 + threadIdx.x;
    const float4* src; __half* dst; int j;
    if (i < 16384)       { src = (const float4*)Wf; dst = g_Wfh; j = i; }
    else if (i < 32768)  { src = (const float4*)Wd; dst = g_Wdh; j = i - 16384; }
    else                 { src = (const float4*)Wi; dst = g_Wih; j = i - 32768; }
    float4 v = src[j];
    uint2 o; o.x = pack2(v.x, v.y); o.y = pack2(v.z, v.w);
    *(uint2*)(dst + j * 4) = o;
}

// ---------------------------------------------------------------------------
// k_init_hmma: g_h0h = leaky(inp @ W_init^T + b).
// fp16 HMMA + ldmatrix fragments, CTA 128x64, 8 warps (4M x 2N), dbl-buffered.
// (g_inph side-write removed: k_id now reads fp32 inp directly.)
// ---------------------------------------------------------------------------
__global__ __launch_bounds__(256, 2) void k_init_hmma(const float* __restrict__ A,
                                                      const float* __restrict__ bias) {
    __shared__ uint32_t As[2][128][20];
    __shared__ uint32_t Ws[2][64][20];
    __shared__ float sb[64];
    const int tid = threadIdx.x;
    const int l = tid & 31, w = tid >> 5;
    const int g = l >> 2, c = l & 3;
    const int wm = w >> 1, wn = w & 1;
    const int rowBase = blockIdx.x * 128;
    const int wr = tid >> 2, wq = tid & 3;

    if (tid < 64) sb[tid] = bias[tid];

    const uint32_t asB = (uint32_t)__cvta_generic_to_shared(&As[0][0][0]);
    const uint32_t wsB = (uint32_t)__cvta_generic_to_shared(&Ws[0][0][0]);
    uint32_t aAddr[2], bAddr[2];
    #pragma unroll
    for (int mt = 0; mt < 2; mt++) {
        int row = wm * 32 + mt * 16 + (l & 15);
        aAddr[mt] = asB + (row * 20 + ((l & 16) ? 4 : 0)) * 4;
    }
    #pragma unroll
    for (int p = 0; p < 2; p++) {
        int row = wn * 32 + p * 16 + (l & 7) + ((l & 16) ? 8 : 0);
        bAddr[p] = wsB + (row * 20 + ((l & 8) ? 4 : 0)) * 4;
    }

    float acc[2][4][4] = {};
    float4 ra[4]; uint4 rw;

    auto ldA = [&](int kc) {
        #pragma unroll
        for (int i = 0; i < 4; i++) {
            int s = tid + i * 256;
            int r = rowBase + (s >> 3); if (r >= R) r = R - 1;
            ra[i] = *(const float4*)(A + (size_t)r * 256 + kc + ((s & 7) << 2));
        }
    };
    auto ldW = [&](int kc) {
        if (wr < 64) rw = *(const uint4*)(g_Wih + (size_t)wr * 256 + kc + wq * 8);
    };
    auto stAW = [&](int buf) {
        #pragma unroll
        for (int i = 0; i < 4; i++) {
            int s = tid + i * 256, r = s >> 3, c4 = s & 7;
            As[buf][r][c4 * 2]     = pack2(ra[i].x, ra[i].y);
            As[buf][r][c4 * 2 + 1] = pack2(ra[i].z, ra[i].w);
        }
        if (wr < 64) {
            Ws[buf][wr][wq * 4 + 0] = rw.x; Ws[buf][wr][wq * 4 + 1] = rw.y;
            Ws[buf][wr][wq * 4 + 2] = rw.z; Ws[buf][wr][wq * 4 + 3] = rw.w;
        }
    };

    ldA(0); ldW(0); stAW(0);
    __syncthreads();

    #pragma unroll 2
    for (int ch = 0; ch < 8; ch++) {
        const int cur = ch & 1;
        if (ch < 7) { ldA((ch + 1) * 32); ldW((ch + 1) * 32); }
        #pragma unroll
        for (int ks = 0; ks < 2; ks++) {
            uint32_t af[2][4], bq[2][4];
            const uint32_t ko = cur * 10240 + ks * 32;
            const uint32_t kw = cur * 5120  + ks * 32;
            ldsm4(af[0], aAddr[0] + ko);
            ldsm4(af[1], aAddr[1] + ko);
            ldsm4(bq[0], bAddr[0] + kw);
            ldsm4(bq[1], bAddr[1] + kw);
            #pragma unroll
            for (int mt = 0; mt < 2; mt++)
                #pragma unroll
                for (int nt = 0; nt < 4; nt++)
                    mma_fp16(acc[mt][nt], af[mt], &bq[nt >> 1][(nt & 1) * 2]);
        }
        if (ch < 7) stAW(cur ^ 1);
        __syncthreads();
    }

    #pragma unroll
    for (int mt = 0; mt < 2; mt++) {
        int r0 = rowBase + wm * 32 + mt * 16 + g;
        #pragma unroll
        for (int nt = 0; nt < 4; nt++) {
            int col = wn * 32 + nt * 8 + c * 2;
            float b0 = sb[col], b1 = sb[col + 1];
            if (r0 < R)
                *(__half2*)(g_h0h + (size_t)r0 * 64 + col) =
                    __floats2half2_rn(leaky(acc[mt][nt][0] + b0), leaky(acc[mt][nt][1] + b1));
            if (r0 + 8 < R)
                *(__half2*)(g_h0h + (size_t)(r0 + 8) * 64 + col) =
                    __floats2half2_rn(leaky(acc[mt][nt][2] + b0), leaky(acc[mt][nt][3] + b1));
        }
    }
}

// ---------------------------------------------------------------------------
// k_id_hmma: out = leaky(inp @ W_id^T + b_id).  Reads fp32 inp directly
// (needs only cvtw) -> launches on its own stream overlapping init+gathers.
// CTA 128x64, 256 thr (low footprint -> co-resident with gather CTAs).
// ---------------------------------------------------------------------------
__global__ __launch_bounds__(256, 2) void k_id_hmma(const float* __restrict__ A,
                                                    const float* __restrict__ bias,
                                                    float* __restrict__ out) {
    __shared__ uint32_t As[2][128][20];
    __shared__ uint32_t Ws[2][64][20];
    __shared__ float sb[64];
    const int tid = threadIdx.x;
    const int l = tid & 31, w = tid >> 5;
    const int g = l >> 2, c = l & 3;
    const int wm = w >> 1, wn = w & 1;
    const int rowBase = (int)(blockIdx.x >> 2) * 128;
    const int colBase = (int)(blockIdx.x & 3) * 64;
    const int wr = tid >> 2, wq = tid & 3;

    if (tid < 64) sb[tid] = bias[colBase + tid];

    const uint32_t asB = (uint32_t)__cvta_generic_to_shared(&As[0][0][0]);
    const uint32_t wsB = (uint32_t)__cvta_generic_to_shared(&Ws[0][0][0]);
    uint32_t aAddr[2], bAddr[2];
    #pragma unroll
    for (int mt = 0; mt < 2; mt++) {
        int row = wm * 32 + mt * 16 + (l & 15);
        aAddr[mt] = asB + (row * 20 + ((l & 16) ? 4 : 0)) * 4;
    }
    #pragma unroll
    for (int p = 0; p < 2; p++) {
        int row = wn * 32 + p * 16 + (l & 7) + ((l & 16) ? 8 : 0);
        bAddr[p] = wsB + (row * 20 + ((l & 8) ? 4 : 0)) * 4;
    }

    float acc[2][4][4] = {};
    float4 ra[4]; uint4 rw;

    auto ldA = [&](int kc) {
        #pragma unroll
        for (int i = 0; i < 4; i++) {
            int s = tid + i * 256;
            int r = rowBase + (s >> 3); if (r >= R) r = R - 1;
            ra[i] = *(const float4*)(A + (size_t)r * 256 + kc + ((s & 7) << 2));
        }
    };
    auto ldW = [&](int kc) {
        if (wr < 64) rw = *(const uint4*)(g_Wdh + (size_t)(colBase + wr) * 256 + kc + wq * 8);
    };
    auto stAW = [&](int buf) {
        #pragma unroll
        for (int i = 0; i < 4; i++) {
            int s = tid + i * 256, r = s >> 3, c4 = s & 7;
            As[buf][r][c4 * 2]     = pack2(ra[i].x, ra[i].y);
            As[buf][r][c4 * 2 + 1] = pack2(ra[i].z, ra[i].w);
        }
        if (wr < 64) {
            Ws[buf][wr][wq * 4 + 0] = rw.x; Ws[buf][wr][wq * 4 + 1] = rw.y;
            Ws[buf][wr][wq * 4 + 2] = rw.z; Ws[buf][wr][wq * 4 + 3] = rw.w;
        }
    };

    ldA(0); ldW(0); stAW(0);
    __syncthreads();

    #pragma unroll 2
    for (int ch = 0; ch < 8; ch++) {
        const int cur = ch & 1;
        if (ch < 7) { ldA((ch + 1) * 32); ldW((ch + 1) * 32); }
        #pragma unroll
        for (int ks = 0; ks < 2; ks++) {
            uint32_t af[2][4], bq[2][4];
            const uint32_t ko = cur * 10240 + ks * 32;
            const uint32_t kw = cur * 5120  + ks * 32;
            ldsm4(af[0], aAddr[0] + ko);
            ldsm4(af[1], aAddr[1] + ko);
            ldsm4(bq[0], bAddr[0] + kw);
            ldsm4(bq[1], bAddr[1] + kw);
            #pragma unroll
            for (int mt = 0; mt < 2; mt++)
                #pragma unroll
                for (int nt = 0; nt < 4; nt++)
                    mma_fp16(acc[mt][nt], af[mt], &bq[nt >> 1][(nt & 1) * 2]);
        }
        if (ch < 7) stAW(cur ^ 1);
        __syncthreads();
    }

    #pragma unroll
    for (int mt = 0; mt < 2; mt++) {
        int r0 = rowBase + wm * 32 + mt * 16 + g;
        #pragma unroll
        for (int nt = 0; nt < 4; nt++) {
            int lc = wn * 32 + nt * 8 + c * 2;
            int col = colBase + lc;
            float b0 = sb[lc], b1 = sb[lc + 1];
            if (r0 < R)
                *(float2*)(out + (size_t)r0 * 256 + col) =
                    make_float2(leaky(acc[mt][nt][0] + b0), leaky(acc[mt][nt][1] + b1));
            if (r0 + 8 < R)
                *(float2*)(out + (size_t)(r0 + 8) * 256 + col) =
                    make_float2(leaky(acc[mt][nt][2] + b0), leaky(acc[mt][nt][3] + b1));
        }
    }
}

// ---------------------------------------------------------------------------
// k_geom: t1_mean (64) and t2_mean (128) per row; leaky per-k before mean.
// ---------------------------------------------------------------------------
__global__ __launch_bounds__(256) void k_geom(const float* __restrict__ G,
                                              const float* __restrict__ Wl1,
                                              const float* __restrict__ bl1,
                                              const float* __restrict__ Wl2,
                                              const float* __restrict__ bl2) {
    __shared__ float sg[64][64];
    __shared__ float sW[192][4];
    __shared__ float sb[192];
    const int tid = threadIdx.x;
    const int rowBase = blockIdx.x * 64;

    for (int t = tid; t < 1024; t += 256) {
        int r = t >> 4, c = t & 15;
        *(float4*)&sg[r][c * 4] = *(const float4*)(G + (size_t)(rowBase + r) * 64 + c * 4);
    }
    if (tid < 64) {
        #pragma unroll
        for (int j = 0; j < 4; j++) sW[tid][j] = Wl1[tid * 4 + j];
        sb[tid] = bl1[tid];
    } else if (tid < 192) {
        int o = tid - 64;
        #pragma unroll
        for (int j = 0; j < 4; j++) sW[tid][j] = Wl2[o * 4 + j];
        sb[tid] = bl2[o];
    }
    __syncthreads();

    const u64 C55 = pk2(0.55f, 0.55f);
    const u64 C45 = pk2(0.45f, 0.45f);

    for (int it = tid; it < 64 * 24; it += 256) {
        int row = it / 24;
        int ob  = (it - row * 24) * 8;
        u64 wp[4][4], bb2[4];
        #pragma unroll
        for (int o = 0; o < 4; o++) {
            #pragma unroll
            for (int j = 0; j < 4; j++)
                wp[j][o] = pk2(sW[ob + 2 * o][j], sW[ob + 2 * o + 1][j]);
            bb2[o] = pk2(sb[ob + 2 * o], sb[ob + 2 * o + 1]);
        }
        u64 acc2[4] = {0ull, 0ull, 0ull, 0ull};
        #pragma unroll
        for (int k = 0; k < 16; k++) {
            float4 gv = *(const float4*)&sg[row][k * 4];
            u64 gx = pk2(gv.x, gv.x), gy = pk2(gv.y, gv.y);
            u64 gz = pk2(gv.z, gv.z), gw = pk2(gv.w, gv.w);
            #pragma unroll
            for (int o = 0; o < 4; o++) {
                u64 d2 = fma2_(gx, wp[0][o], fma2_(gy, wp[1][o],
                         fma2_(gz, wp[2][o], fma2_(gw, wp[3][o], bb2[o]))));
                u64 a2 = d2 & 0x7FFFFFFF7FFFFFFFull;
                acc2[o] = fma2_(C55, d2, acc2[o]);
                acc2[o] = fma2_(C45, a2, acc2[o]);
            }
        }
        size_t gr = (size_t)(rowBase + row);
        #pragma unroll
        for (int o = 0; o < 4; o++) {
            float v0, v1; upk2(acc2[o], v0, v1);
            __half2 h = __floats2half2_rn(v0 * 0.0625f, v1 * 0.0625f);
            int oo = ob + o * 2;
            if (oo < 64) *(__half2*)(g_x1h  + gr * 128 + oo)      = h;
            else         *(__half2*)(g_t2mh + gr * 128 + oo - 64) = h;
        }
    }
}

// ---------------------------------------------------------------------------
// k_gather1: x1[r,64:128] = mean_k h0[batch(r), idx[r,k], :64]   (fp16 rows)
// ---------------------------------------------------------------------------
__global__ __launch_bounds__(256) void k_gather1(const int* __restrict__ idx) {
    int row  = blockIdx.x * 8 + (threadIdx.x >> 5);
    int lane = threadIdx.x & 31;
    if (row >= R) return;
    const int* ip = idx + (size_t)row * 16;
    int ipv = ip[lane & 15];
    const __half2* base = (const __half2*)g_h0h + (size_t)(row / Np) * Np * 32 + lane;
    float ax = 0.f, ay = 0.f;
    #pragma unroll
    for (int k = 0; k < 16; k++) {
        int s = __shfl_sync(0xffffffffu, ipv, k);
        float2 v = __half22float2(base[(size_t)s * 32]);
        ax += v.x; ay += v.y;
    }
    *((__half2*)g_x1h + (size_t)row * 64 + 32 + lane) =
        __floats2half2_rn(ax * 0.0625f, ay * 0.0625f);
}

// ---------------------------------------------------------------------------
// k_gather2: x2[r] = [ t2m[r] | mean_k x1[batch(r), idx[r,k], :128] ] (fp16)
// ---------------------------------------------------------------------------
__global__ __launch_bounds__(256) void k_gather2(const int* __restrict__ idx) {
    int row  = blockIdx.x * 8 + (threadIdx.x >> 5);
    int lane = threadIdx.x & 31;
    if (row >= R) return;
    const int* ip = idx + (size_t)row * 16;
    int ipv = ip[lane & 15];
    const uint2* base = (const uint2*)(g_x1h + (size_t)(row / Np) * Np * 128) + lane;
    float a0 = 0.f, a1 = 0.f, a2 = 0.f, a3 = 0.f;
    #pragma unroll
    for (int k = 0; k < 16; k++) {
        int s = __shfl_sync(0xffffffffu, ipv, k);
        uint2 v = base[(size_t)s * 32];
        float2 f0 = __half22float2(*(__half2*)&v.x);
        float2 f1 = __half22float2(*(__half2*)&v.y);
        a0 += f0.x; a1 += f0.y; a2 += f1.x; a3 += f1.y;
    }
    uint2 t = ((const uint2*)(g_t2mh + (size_t)row * 128))[lane];
    ((uint2*)(g_x2h + (size_t)row * 256))[lane] = t;
    __half2 p0 = __floats2half2_rn(a0 * 0.0625f, a1 * 0.0625f);
    __half2 p1 = __floats2half2_rn(a2 * 0.0625f, a3 * 0.0625f);
    uint2 o; o.x = *(uint32_t*)&p0; o.y = *(uint32_t*)&p1;
    ((uint2*)(g_x2h + (size_t)row * 256 + 128))[lane] = o;
}

// ---------------------------------------------------------------------------
// k_final0_hmma: out = leaky(x2 @ Wf^T + bf) + out   (out holds the k_id
// term; IEEE + is commutative -> bitwise-identical to the fused version).
// CTA 128x64, 256 thr, fp16 ldmatrix HMMA, double-buffered.
// ---------------------------------------------------------------------------
__global__ __launch_bounds__(256, 2) void k_final0_hmma(const __half* __restrict__ x2h,
                                                        const float* __restrict__ bf,
                                                        float* __restrict__ out) {
    __shared__ uint32_t As[2][128][20];
    __shared__ uint32_t Ws[2][64][20];
    __shared__ float sb[64];
    const int tid = threadIdx.x;
    const int l = tid & 31, w = tid >> 5;
    const int g = l >> 2, c = l & 3;
    const int wm = w >> 1, wn = w & 1;
    const int rowBase = (int)(blockIdx.x >> 2) * 128;
    const int colBase = (int)(blockIdx.x & 3) * 64;
    const int ar = tid >> 2, aq = tid & 3;

    if (tid < 64) sb[tid] = bf[colBase + tid];

    const uint32_t asB = (uint32_t)__cvta_generic_to_shared(&As[0][0][0]);
    const uint32_t wsB = (uint32_t)__cvta_generic_to_shared(&Ws[0][0][0]);
    uint32_t aAddr[2], bAddr[2];
    #pragma unroll
    for (int mt = 0; mt < 2; mt++) {
        int row = wm * 32 + mt * 16 + (l & 15);
        aAddr[mt] = asB + (row * 20 + ((l & 16) ? 4 : 0)) * 4;
    }
    #pragma unroll
    for (int p = 0; p < 2; p++) {
        int row = wn * 32 + p * 16 + (l & 7) + ((l & 16) ? 8 : 0);
        bAddr[p] = wsB + (row * 20 + ((l & 8) ? 4 : 0)) * 4;
    }

    float acc[2][4][4] = {};
    uint4 ra[2], rw;
    int gr0 = rowBase + ar;      if (gr0 >= R) gr0 = R - 1;
    int gr1 = rowBase + ar + 64; if (gr1 >= R) gr1 = R - 1;

    auto ld = [&](int kc) {
        ra[0] = *(const uint4*)(x2h + (size_t)gr0 * 256 + kc + aq * 8);
        ra[1] = *(const uint4*)(x2h + (size_t)gr1 * 256 + kc + aq * 8);
        if (ar < 64) rw = *(const uint4*)(g_Wfh + (size_t)(colBase + ar) * 256 + kc + aq * 8);
    };
    auto st = [&](int buf) {
        #pragma unroll
        for (int i = 0; i < 2; i++) {
            int r = ar + i * 64;
            As[buf][r][aq * 4 + 0] = ra[i].x; As[buf][r][aq * 4 + 1] = ra[i].y;
            As[buf][r][aq * 4 + 2] = ra[i].z; As[buf][r][aq * 4 + 3] = ra[i].w;
        }
        if (ar < 64) {
            Ws[buf][ar][aq * 4 + 0] = rw.x; Ws[buf][ar][aq * 4 + 1] = rw.y;
            Ws[buf][ar][aq * 4 + 2] = rw.z; Ws[buf][ar][aq * 4 + 3] = rw.w;
        }
    };

    ld(0); st(0);
    __syncthreads();

    #pragma unroll 2
    for (int ch = 0; ch < 8; ch++) {
        const int cur = ch & 1;
        if (ch < 7) ld((ch + 1) * 32);
        #pragma unroll
        for (int ks = 0; ks < 2; ks++) {
            uint32_t af[2][4], bq[2][4];
            const uint32_t ko = cur * 10240 + ks * 32;
            const uint32_t kw = cur * 5120  + ks * 32;
            ldsm4(af[0], aAddr[0] + ko);
            ldsm4(af[1], aAddr[1] + ko);
            ldsm4(bq[0], bAddr[0] + kw);
            ldsm4(bq[1], bAddr[1] + kw);
            #pragma unroll
            for (int mt = 0; mt < 2; mt++)
                #pragma unroll
                for (int nt = 0; nt < 4; nt++)
                    mma_fp16(acc[mt][nt], af[mt], &bq[nt >> 1][(nt & 1) * 2]);
        }
        if (ch < 7) st(cur ^ 1);
        __syncthreads();
    }

    #pragma unroll
    for (int mt = 0; mt < 2; mt++) {
        int r0 = rowBase + wm * 32 + mt * 16 + g;
        #pragma unroll
        for (int nt = 0; nt < 4; nt++) {
            int lc = wn * 32 + nt * 8 + c * 2;
            int col = colBase + lc;
            float b0 = sb[lc], b1 = sb[lc + 1];
            const float* a = acc[mt][nt];
            if (r0 < R) {
                float* p = out + (size_t)r0 * 256 + col;
                float2 q = *(const float2*)p;
                *(float2*)p = make_float2(leaky(a[0] + b0) + q.x,
                                          leaky(a[1] + b1) + q.y);
            }
            if (r0 + 8 < R) {
                float* p = out + (size_t)(r0 + 8) * 256 + col;
                float2 q = *(const float2*)p;
                *(float2*)p = make_float2(leaky(a[2] + b0) + q.x,
                                          leaky(a[3] + b1) + q.y);
            }
        }
    }
}

// ---------------------------------------------------------------------------
extern "C" void kernel_launch(void* const* d_in, const int* in_sizes, int n_in,
                              void* d_out, int out_size) {
    const float* inp    = (const float*)d_in[0];   // [2,20000,256]
    const float* geom   = (const float*)d_in[1];   // [2,20000,16,4]
    const int*   idx    = (const int*)  d_in[2];   // [2,20000,16] int32
    const float* W_init = (const float*)d_in[3];
    const float* b_init = (const float*)d_in[4];
    const float* W_l1   = (const float*)d_in[5];
    const float* b_l1   = (const float*)d_in[6];
    const float* W_l2   = (const float*)d_in[7];
    const float* b_l2   = (const float*)d_in[8];
    const float* W_fin  = (const float*)d_in[9];
    const float* b_fin  = (const float*)d_in[10];
    const float* W_id   = (const float*)d_in[11];
    const float* b_id   = (const float*)d_in[12];
    float* out = (float*)d_out;

    __half* x2h; cudaGetSymbolAddress((void**)&x2h, g_x2h);

    static cudaStream_t s2 = nullptr, s3 = nullptr;
    static cudaEvent_t eFork = nullptr, eJoin = nullptr, eCvt = nullptr, eId = nullptr;
    if (!s2) {
        cudaStreamCreateWithFlags(&s2, cudaStreamNonBlocking);
        cudaStreamCreateWithFlags(&s3, cudaStreamNonBlocking);
        cudaEventCreateWithFlags(&eFork, cudaEventDisableTiming);
        cudaEventCreateWithFlags(&eJoin, cudaEventDisableTiming);
        cudaEventCreateWithFlags(&eCvt,  cudaEventDisableTiming);
        cudaEventCreateWithFlags(&eId,   cudaEventDisableTiming);
    }

    const int rowTiles = (R + 127) / 128;   // 313

    // Fork k_geom (independent until gather2).
    cudaEventRecord(eFork, 0);
    cudaStreamWaitEvent(s2, eFork, 0);
    k_geom<<<R / 64, 256, 0, s2>>>(geom, W_l1, b_l1, W_l2, b_l2);
    cudaEventRecord(eJoin, s2);

    // Main chain: weights first.
    k_cvtw<<<144, 256>>>(W_fin, W_id, W_init);
    cudaEventRecord(eCvt, 0);

    // Fork k_id: residual-MLP term straight into out, overlapping the whole
    // init/gather chain. Small CTA footprint -> co-resident with gathers.
    cudaStreamWaitEvent(s3, eCvt, 0);
    k_id_hmma<<<rowTiles * 4, 256, 0, s3>>>(inp, b_id, out);
    cudaEventRecord(eId, s3);

    k_init_hmma<<<rowTiles, 256>>>(inp, b_init);
    k_gather1  <<<R / 8,  256>>>(idx);
    cudaStreamWaitEvent(0, eJoin, 0);
    k_gather2  <<<R / 8,  256>>>(idx);
    cudaStreamWaitEvent(0, eId, 0);
    k_final0_hmma<<<rowTiles * 4, 256>>>(x2h, b_fin, out);
}

// round 15
// speedup vs baseline: 1.0640x; 1.0640x over previous
#include <cuda_runtime.h>
#include <cstdint>
#include <cuda_fp16.h>

// Problem constants (fixed by the reference).
constexpr int Bn = 2;
constexpr int Np = 20000;
constexpr int R  = Bn * Np;       // 40000 point rows

// Scratch (allocation-free rule: __device__ globals).
__device__ __half g_h0h [R * 64];    // leaky(inp @ W_init^T + b)      [R,64]
__device__ __half g_x1h [R * 128];   // [t1_mean | fn1_mean]           [R,128]
__device__ __half g_x2h [R * 256];   // [t2_mean | fn2_mean]           [R,256]
__device__ __half g_inph[R * 256];   // fp16 copy of input (written by k_init)
__device__ __half g_Wfh [256 * 256]; // fp16 W_fin
__device__ __half g_Wdh [256 * 256]; // fp16 W_id
__device__ __half g_Wih [64 * 256];  // fp16 W_init

__device__ __forceinline__ float leaky(float x) { return x > 0.f ? x : 0.1f * x; }

__device__ __forceinline__ uint32_t pack2(float a, float b) {
    __half2 h = __floats2half2_rn(a, b);
    return *reinterpret_cast<uint32_t*>(&h);
}
// m16n8k16 row.col f32 <- f16*f16 + f32 (base ISA, sm_80+).
__device__ __forceinline__ void mma_fp16(float* c, const uint32_t* a, const uint32_t* b) {
    asm volatile(
        "mma.sync.aligned.m16n8k16.row.col.f32.f16.f16.f32 "
        "{%0,%1,%2,%3},{%4,%5,%6,%7},{%8,%9},{%0,%1,%2,%3};"
        : "+f"(c[0]), "+f"(c[1]), "+f"(c[2]), "+f"(c[3])
        : "r"(a[0]), "r"(a[1]), "r"(a[2]), "r"(a[3]), "r"(b[0]), "r"(b[1]));
}
// ldmatrix x4 (base ISA, sm_75+).
__device__ __forceinline__ void ldsm4(uint32_t* r, uint32_t addr) {
    asm volatile("ldmatrix.sync.aligned.m8n8.x4.shared.b16 {%0,%1,%2,%3}, [%4];"
                 : "=r"(r[0]), "=r"(r[1]), "=r"(r[2]), "=r"(r[3]) : "r"(addr));
}
// cp.async 16B (base ISA, sm_80+).
__device__ __forceinline__ void cpasync16(uint32_t saddr, const void* gptr) {
    asm volatile("cp.async.ca.shared.global [%0], [%1], 16;"
                 :: "r"(saddr), "l"(gptr) : "memory");
}
#define CP_COMMIT() asm volatile("cp.async.commit_group;" ::: "memory")
#define CP_WAIT1()  asm volatile("cp.async.wait_group 1;" ::: "memory")

// Packed fp32x2 FMA (PTX ISA sm_100+, base target).
typedef unsigned long long u64;
__device__ __forceinline__ u64 pk2(float x, float y) {
    u64 r; asm("mov.b64 %0, {%1, %2};" : "=l"(r) : "f"(x), "f"(y)); return r;
}
__device__ __forceinline__ void upk2(u64 v, float& x, float& y) {
    asm("mov.b64 {%0, %1}, %2;" : "=f"(x), "=f"(y) : "l"(v));
}
__device__ __forceinline__ u64 fma2_(u64 a, u64 b, u64 c) {
    u64 d; asm("fma.rn.f32x2 %0, %1, %2, %3;" : "=l"(d) : "l"(a), "l"(b), "l"(c));
    return d;
}

// ---------------------------------------------------------------------------
// k_cvtw: one-shot fp32 -> fp16 conversion of the three GEMM weight matrices.
// ---------------------------------------------------------------------------
__global__ __launch_bounds__(256) void k_cvtw(const float* __restrict__ Wf,
                                              const float* __restrict__ Wd,
                                              const float* __restrict__ Wi) {
    int i = blockIdx.x * 256 + threadIdx.x;
    const float4* src; __half* dst; int j;
    if (i < 16384)       { src = (const float4*)Wf; dst = g_Wfh; j = i; }
    else if (i < 32768)  { src = (const float4*)Wd; dst = g_Wdh; j = i - 16384; }
    else                 { src = (const float4*)Wi; dst = g_Wih; j = i - 32768; }
    float4 v = src[j];
    uint2 o; o.x = pack2(v.x, v.y); o.y = pack2(v.z, v.w);
    *(uint2*)(dst + j * 4) = o;
}

// ---------------------------------------------------------------------------
// k_init_hmma: g_h0h = leaky(inp @ W_init^T + b). Emits g_inph as side product.
// M-tile 64 (grid 625 -> ~4 waves at 2 CTAs/SM: wave-pipelined latency hiding;
// the old 313-CTA grid was a single wave bound by one CTA's serial chain).
// 8 warps (4M x 2N), warp tile 16x32, double-buffered, ldmatrix fragments.
// ---------------------------------------------------------------------------
__global__ __launch_bounds__(256, 2) void k_init_hmma(const float* __restrict__ A,
                                                      const float* __restrict__ bias) {
    __shared__ uint32_t As[2][64][20];
    __shared__ uint32_t Ws[2][64][20];
    __shared__ float sb[64];
    const int tid = threadIdx.x;
    const int l = tid & 31, w = tid >> 5;
    const int g = l >> 2, c = l & 3;
    const int wm = w >> 1, wn = w & 1;     // wm 0..3 (16 rows each), wn 0..1
    const int rowBase = blockIdx.x * 64;
    const int wr = tid >> 2, wq = tid & 3;

    if (tid < 64) sb[tid] = bias[tid];

    const uint32_t asB = (uint32_t)__cvta_generic_to_shared(&As[0][0][0]);
    const uint32_t wsB = (uint32_t)__cvta_generic_to_shared(&Ws[0][0][0]);
    uint32_t aAddr, bAddr[2];
    {
        int row = wm * 16 + (l & 15);
        aAddr = asB + (row * 20 + ((l & 16) ? 4 : 0)) * 4;
    }
    #pragma unroll
    for (int p = 0; p < 2; p++) {
        int row = wn * 32 + p * 16 + (l & 7) + ((l & 16) ? 8 : 0);
        bAddr[p] = wsB + (row * 20 + ((l & 8) ? 4 : 0)) * 4;
    }

    float acc[4][4] = {};
    float4 ra[2]; uint4 rw;

    auto ldA = [&](int kc) {
        #pragma unroll
        for (int i = 0; i < 2; i++) {
            int s = tid + i * 256;
            int r = rowBase + (s >> 3); if (r >= R) r = R - 1;
            ra[i] = *(const float4*)(A + (size_t)r * 256 + kc + ((s & 7) << 2));
        }
    };
    auto ldW = [&](int kc) {
        rw = *(const uint4*)(g_Wih + (size_t)wr * 256 + kc + wq * 8);
    };
    auto stAW = [&](int buf, int kc) {
        #pragma unroll
        for (int i = 0; i < 2; i++) {
            int s = tid + i * 256, r = s >> 3, c4 = s & 7;
            uint32_t p0 = pack2(ra[i].x, ra[i].y);
            uint32_t p1 = pack2(ra[i].z, ra[i].w);
            As[buf][r][c4 * 2]     = p0;
            As[buf][r][c4 * 2 + 1] = p1;
            int gr = rowBase + r; if (gr >= R) gr = R - 1;
            uint2 w2; w2.x = p0; w2.y = p1;
            *(uint2*)(g_inph + (size_t)gr * 256 + kc + (c4 << 2)) = w2;
        }
        Ws[buf][wr][wq * 4 + 0] = rw.x; Ws[buf][wr][wq * 4 + 1] = rw.y;
        Ws[buf][wr][wq * 4 + 2] = rw.z; Ws[buf][wr][wq * 4 + 3] = rw.w;
    };

    ldA(0); ldW(0); stAW(0, 0);
    __syncthreads();

    #pragma unroll 2
    for (int ch = 0; ch < 8; ch++) {
        const int cur = ch & 1;
        if (ch < 7) { ldA((ch + 1) * 32); ldW((ch + 1) * 32); }
        #pragma unroll
        for (int ks = 0; ks < 2; ks++) {
            uint32_t af[4], bq[2][4];
            const uint32_t ko = cur * 5120 + ks * 32;    // stage stride 64*20*4
            ldsm4(af, aAddr + ko);
            ldsm4(bq[0], bAddr[0] + ko);
            ldsm4(bq[1], bAddr[1] + ko);
            #pragma unroll
            for (int nt = 0; nt < 4; nt++)
                mma_fp16(acc[nt], af, &bq[nt >> 1][(nt & 1) * 2]);
        }
        if (ch < 7) stAW(cur ^ 1, (ch + 1) * 32);
        __syncthreads();
    }

    int r0 = rowBase + wm * 16 + g;
    #pragma unroll
    for (int nt = 0; nt < 4; nt++) {
        int col = wn * 32 + nt * 8 + c * 2;
        float b0 = sb[col], b1 = sb[col + 1];
        if (r0 < R)
            *(__half2*)(g_h0h + (size_t)r0 * 64 + col) =
                __floats2half2_rn(leaky(acc[nt][0] + b0), leaky(acc[nt][1] + b1));
        if (r0 + 8 < R)
            *(__half2*)(g_h0h + (size_t)(r0 + 8) * 64 + col) =
                __floats2half2_rn(leaky(acc[nt][2] + b0), leaky(acc[nt][3] + b1));
    }
}

// ---------------------------------------------------------------------------
// k_geom: t1_mean -> g_x1h[:,0:64]; t2_mean -> g_x2h[:,0:128] DIRECTLY
// (gather2 no longer copies it through).
// ---------------------------------------------------------------------------
__global__ __launch_bounds__(256) void k_geom(const float* __restrict__ G,
                                              const float* __restrict__ Wl1,
                                              const float* __restrict__ bl1,
                                              const float* __restrict__ Wl2,
                                              const float* __restrict__ bl2) {
    __shared__ float sg[64][64];
    __shared__ float sW[192][4];
    __shared__ float sb[192];
    const int tid = threadIdx.x;
    const int rowBase = blockIdx.x * 64;

    for (int t = tid; t < 1024; t += 256) {
        int r = t >> 4, c = t & 15;
        *(float4*)&sg[r][c * 4] = *(const float4*)(G + (size_t)(rowBase + r) * 64 + c * 4);
    }
    if (tid < 64) {
        #pragma unroll
        for (int j = 0; j < 4; j++) sW[tid][j] = Wl1[tid * 4 + j];
        sb[tid] = bl1[tid];
    } else if (tid < 192) {
        int o = tid - 64;
        #pragma unroll
        for (int j = 0; j < 4; j++) sW[tid][j] = Wl2[o * 4 + j];
        sb[tid] = bl2[o];
    }
    __syncthreads();

    const u64 C55 = pk2(0.55f, 0.55f);
    const u64 C45 = pk2(0.45f, 0.45f);

    for (int it = tid; it < 64 * 24; it += 256) {
        int row = it / 24;
        int ob  = (it - row * 24) * 8;
        u64 wp[4][4], bb2[4];
        #pragma unroll
        for (int o = 0; o < 4; o++) {
            #pragma unroll
            for (int j = 0; j < 4; j++)
                wp[j][o] = pk2(sW[ob + 2 * o][j], sW[ob + 2 * o + 1][j]);
            bb2[o] = pk2(sb[ob + 2 * o], sb[ob + 2 * o + 1]);
        }
        u64 acc2[4] = {0ull, 0ull, 0ull, 0ull};
        #pragma unroll
        for (int k = 0; k < 16; k++) {
            float4 gv = *(const float4*)&sg[row][k * 4];
            u64 gx = pk2(gv.x, gv.x), gy = pk2(gv.y, gv.y);
            u64 gz = pk2(gv.z, gv.z), gw = pk2(gv.w, gv.w);
            #pragma unroll
            for (int o = 0; o < 4; o++) {
                u64 d2 = fma2_(gx, wp[0][o], fma2_(gy, wp[1][o],
                         fma2_(gz, wp[2][o], fma2_(gw, wp[3][o], bb2[o]))));
                u64 a2 = d2 & 0x7FFFFFFF7FFFFFFFull;
                acc2[o] = fma2_(C55, d2, acc2[o]);
                acc2[o] = fma2_(C45, a2, acc2[o]);
            }
        }
        size_t gr = (size_t)(rowBase + row);
        #pragma unroll
        for (int o = 0; o < 4; o++) {
            float v0, v1; upk2(acc2[o], v0, v1);
            __half2 h = __floats2half2_rn(v0 * 0.0625f, v1 * 0.0625f);
            int oo = ob + o * 2;
            if (oo < 64) *(__half2*)(g_x1h + gr * 128 + oo)        = h;
            else         *(__half2*)(g_x2h + gr * 256 + (oo - 64)) = h;
        }
    }
}

// ---------------------------------------------------------------------------
// k_gather1: x1[r,64:128] = mean_k h0[batch(r), idx[r,k], :64]   (fp16 rows)
// ---------------------------------------------------------------------------
__global__ __launch_bounds__(256) void k_gather1(const int* __restrict__ idx) {
    int row  = blockIdx.x * 8 + (threadIdx.x >> 5);
    int lane = threadIdx.x & 31;
    if (row >= R) return;
    const int* ip = idx + (size_t)row * 16;
    int ipv = ip[lane & 15];
    const __half2* base = (const __half2*)g_h0h + (size_t)(row / Np) * Np * 32 + lane;
    float ax = 0.f, ay = 0.f;
    #pragma unroll
    for (int k = 0; k < 16; k++) {
        int s = __shfl_sync(0xffffffffu, ipv, k);
        float2 v = __half22float2(base[(size_t)s * 32]);
        ax += v.x; ay += v.y;
    }
    *((__half2*)g_x1h + (size_t)row * 64 + 32 + lane) =
        __floats2half2_rn(ax * 0.0625f, ay * 0.0625f);
}

// ---------------------------------------------------------------------------
// k_gather2: x2[r,128:256] = mean_k x1[batch(r), idx[r,k], :128]  (fp16)
// (t2_mean half of x2 is written directly by k_geom.)
// ---------------------------------------------------------------------------
__global__ __launch_bounds__(256) void k_gather2(const int* __restrict__ idx) {
    int row  = blockIdx.x * 8 + (threadIdx.x >> 5);
    int lane = threadIdx.x & 31;
    if (row >= R) return;
    const int* ip = idx + (size_t)row * 16;
    int ipv = ip[lane & 15];
    const uint2* base = (const uint2*)(g_x1h + (size_t)(row / Np) * Np * 128) + lane;
    float a0 = 0.f, a1 = 0.f, a2 = 0.f, a3 = 0.f;
    #pragma unroll
    for (int k = 0; k < 16; k++) {
        int s = __shfl_sync(0xffffffffu, ipv, k);
        uint2 v = base[(size_t)s * 32];
        float2 f0 = __half22float2(*(__half2*)&v.x);
        float2 f1 = __half22float2(*(__half2*)&v.y);
        a0 += f0.x; a1 += f0.y; a2 += f1.x; a3 += f1.y;
    }
    __half2 p0 = __floats2half2_rn(a0 * 0.0625f, a1 * 0.0625f);
    __half2 p1 = __floats2half2_rn(a2 * 0.0625f, a3 * 0.0625f);
    uint2 o; o.x = *(uint32_t*)&p0; o.y = *(uint32_t*)&p1;
    ((uint2*)(g_x2h + (size_t)row * 256 + 128))[lane] = o;
}

// ---------------------------------------------------------------------------
// k_final_hmma: out = leaky(x2 @ Wf^T + bf) + leaky(inp @ Wi^T + bi)
// fp16 HMMA, CTA 128x64, 256 thr, 2 CTAs/SM. Single 16-chunk mainloop
// (phase = ch>>3, fully unrolled) with 3-stage cp.async pipeline.
// Dual-phase register accumulators, ldmatrix fragments, single fused write.
// ---------------------------------------------------------------------------
__global__ __launch_bounds__(256, 2) void k_final_hmma(const __half* __restrict__ x2h,
                                                       const __half* __restrict__ inph,
                                                       const float* __restrict__ bf,
                                                       const float* __restrict__ bd,
                                                       float* __restrict__ out) {
    __shared__ uint32_t As[3][128][20];   // 3-stage, 10240B/stage
    __shared__ uint32_t Bs[3][64][20];    // 3-stage, 5120B/stage
    __shared__ float sbias[2][64];
    const int tid = threadIdx.x;
    const int l = tid & 31, w = tid >> 5;
    const int g = l >> 2, c = l & 3;
    const int wm = w >> 1, wn = w & 1;
    const int rowBase = (int)(blockIdx.x >> 2) * 128;
    const int colBase = (int)(blockIdx.x & 3) * 64;

    if (tid < 128) {
        int p = tid >> 6, j = tid & 63;
        sbias[p][j] = p ? bd[colBase + j] : bf[colBase + j];
    }

    const uint32_t asB = (uint32_t)__cvta_generic_to_shared(&As[0][0][0]);
    const uint32_t bsB = (uint32_t)__cvta_generic_to_shared(&Bs[0][0][0]);
    uint32_t aAddr[2], bAddr[2];
    #pragma unroll
    for (int mt = 0; mt < 2; mt++) {
        int row = wm * 32 + mt * 16 + (l & 15);
        aAddr[mt] = asB + (row * 20 + ((l & 16) ? 4 : 0)) * 4;
    }
    #pragma unroll
    for (int p = 0; p < 2; p++) {
        int row = wn * 32 + p * 16 + (l & 7) + ((l & 16) ? 8 : 0);
        bAddr[p] = bsB + (row * 20 + ((l & 8) ? 4 : 0)) * 4;
    }

    const int ar = tid >> 2, aq = tid & 3;
    int gr0 = rowBase + ar;      if (gr0 >= R) gr0 = R - 1;
    int gr1 = rowBase + ar + 64; if (gr1 >= R) gr1 = R - 1;

    auto issue = [&](int ch, int stg) {
        const int p = ch >> 3, kc = (ch & 7) << 5;
        const __half* A = p ? inph : x2h;
        const __half* W = p ? g_Wdh : g_Wfh;
        cpasync16(asB + stg * 10240 + ar * 80 + aq * 16,
                  A + (size_t)gr0 * 256 + kc + aq * 8);
        cpasync16(asB + stg * 10240 + (ar + 64) * 80 + aq * 16,
                  A + (size_t)gr1 * 256 + kc + aq * 8);
        cpasync16(bsB + stg * 5120 + ar * 80 + aq * 16,
                  W + (size_t)(colBase + ar) * 256 + kc + aq * 8);
    };

    float acc[2][8][4] = {};   // [phase][mt*4+nt][frag] — statically indexed

    issue(0, 0); CP_COMMIT();
    issue(1, 1); CP_COMMIT();

    #pragma unroll
    for (int ch = 0; ch < 16; ch++) {
        const int stg  = ch % 3;
        const int ph   = ch >> 3;
        CP_WAIT1();
        __syncthreads();
        #pragma unroll
        for (int ks = 0; ks < 2; ks++) {
            uint32_t af[2][4], bq[2][4];
            const uint32_t ko = stg * 10240 + ks * 32;
            const uint32_t kw = stg * 5120  + ks * 32;
            ldsm4(af[0], aAddr[0] + ko);
            ldsm4(af[1], aAddr[1] + ko);
            ldsm4(bq[0], bAddr[0] + kw);
            ldsm4(bq[1], bAddr[1] + kw);
            #pragma unroll
            for (int mt = 0; mt < 2; mt++)
                #pragma unroll
                for (int nt = 0; nt < 4; nt++)
                    mma_fp16(acc[ph][mt * 4 + nt], af[mt], &bq[nt >> 1][(nt & 1) * 2]);
        }
        __syncthreads();
        if (ch < 14) issue(ch + 2, (ch + 2) % 3);
        CP_COMMIT();
    }

    // Fused epilogue: single write of out.
    #pragma unroll
    for (int mt = 0; mt < 2; mt++) {
        int r0 = rowBase + wm * 32 + mt * 16 + g;
        #pragma unroll
        for (int nt = 0; nt < 4; nt++) {
            int lc = wn * 32 + nt * 8 + c * 2;
            int col = colBase + lc;
            float bf0 = sbias[0][lc], bf1 = sbias[0][lc + 1];
            float bd0 = sbias[1][lc], bd1 = sbias[1][lc + 1];
            const float* a0 = acc[0][mt * 4 + nt];
            const float* a1 = acc[1][mt * 4 + nt];
            if (r0 < R)
                *(float2*)(out + (size_t)r0 * 256 + col) = make_float2(
                    leaky(a0[0] + bf0) + leaky(a1[0] + bd0),
                    leaky(a0[1] + bf1) + leaky(a1[1] + bd1));
            if (r0 + 8 < R)
                *(float2*)(out + (size_t)(r0 + 8) * 256 + col) = make_float2(
                    leaky(a0[2] + bf0) + leaky(a1[2] + bd0),
                    leaky(a0[3] + bf1) + leaky(a1[3] + bd1));
        }
    }
}

// ---------------------------------------------------------------------------
extern "C" void kernel_launch(void* const* d_in, const int* in_sizes, int n_in,
                              void* d_out, int out_size) {
    const float* inp    = (const float*)d_in[0];   // [2,20000,256]
    const float* geom   = (const float*)d_in[1];   // [2,20000,16,4]
    const int*   idx    = (const int*)  d_in[2];   // [2,20000,16] int32
    const float* W_init = (const float*)d_in[3];
    const float* b_init = (const float*)d_in[4];
    const float* W_l1   = (const float*)d_in[5];
    const float* b_l1   = (const float*)d_in[6];
    const float* W_l2   = (const float*)d_in[7];
    const float* b_l2   = (const float*)d_in[8];
    const float* W_fin  = (const float*)d_in[9];
    const float* b_fin  = (const float*)d_in[10];
    const float* W_id   = (const float*)d_in[11];
    const float* b_id   = (const float*)d_in[12];
    float* out = (float*)d_out;

    __half* x2h;  cudaGetSymbolAddress((void**)&x2h,  g_x2h);
    __half* inph; cudaGetSymbolAddress((void**)&inph, g_inph);

    static cudaStream_t s2 = nullptr;
    static cudaEvent_t eFork = nullptr, eJoin = nullptr;
    if (!s2) {
        cudaStreamCreateWithFlags(&s2, cudaStreamNonBlocking);
        cudaEventCreateWithFlags(&eFork, cudaEventDisableTiming);
        cudaEventCreateWithFlags(&eJoin, cudaEventDisableTiming);
        cudaFuncSetAttribute(k_final_hmma,
                             cudaFuncAttributePreferredSharedMemoryCarveout, 100);
    }

    // Fork: k_geom is independent of the k_init chain until gather2/final.
    cudaEventRecord(eFork, 0);
    cudaStreamWaitEvent(s2, eFork, 0);
    k_geom<<<R / 64, 256, 0, s2>>>(geom, W_l1, b_l1, W_l2, b_l2);
    cudaEventRecord(eJoin, s2);

    // Main chain.
    k_cvtw      <<<144, 256>>>(W_fin, W_id, W_init);
    k_init_hmma <<<(R + 63) / 64, 256>>>(inp, b_init);
    k_gather1   <<<R / 8,  256>>>(idx);
    cudaStreamWaitEvent(0, eJoin, 0);
    k_gather2   <<<R / 8,  256>>>(idx);
    k_final_hmma<<<((R + 127) / 128) * 4, 256>>>(x2h, inph, b_fin, b_id, out);
}

// round 16
// speedup vs baseline: 1.1435x; 1.0748x over previous
#include <cuda_runtime.h>
#include <cstdint>
#include <cuda_fp16.h>

// Problem constants (fixed by the reference).
constexpr int Bn = 2;
constexpr int Np = 20000;
constexpr int R  = Bn * Np;       // 40000 point rows

// Scratch (allocation-free rule: __device__ globals).
__device__ __half g_h0h [R * 64];    // leaky(inp @ W_init^T + b)      [R,64]
__device__ __half g_x1h [R * 128];   // [t1_mean | fn1_mean]           [R,128]
__device__ __half g_t2mh[R * 128];   // mean_k leaky(geom @ Wl2^T + b) [R,128]
__device__ __half g_x2h [R * 256];   // [t2_mean | fn2_mean]           [R,256]
__device__ __half g_inph[R * 256];   // fp16 copy of input (written by k_init)
__device__ __half g_Wfh [256 * 256]; // fp16 W_fin
__device__ __half g_Wdh [256 * 256]; // fp16 W_id
__device__ __half g_Wih [64 * 256];  // fp16 W_init

__device__ __forceinline__ float leaky(float x) { return x > 0.f ? x : 0.1f * x; }

__device__ __forceinline__ uint32_t pack2(float a, float b) {
    __half2 h = __floats2half2_rn(a, b);
    return *reinterpret_cast<uint32_t*>(&h);
}
// m16n8k16 row.col f32 <- f16*f16 + f32 (base ISA, sm_80+).
__device__ __forceinline__ void mma_fp16(float* c, const uint32_t* a, const uint32_t* b) {
    asm volatile(
        "mma.sync.aligned.m16n8k16.row.col.f32.f16.f16.f32 "
        "{%0,%1,%2,%3},{%4,%5,%6,%7},{%8,%9},{%0,%1,%2,%3};"
        : "+f"(c[0]), "+f"(c[1]), "+f"(c[2]), "+f"(c[3])
        : "r"(a[0]), "r"(a[1]), "r"(a[2]), "r"(a[3]), "r"(b[0]), "r"(b[1]));
}
// ldmatrix x4 (base ISA, sm_75+).
__device__ __forceinline__ void ldsm4(uint32_t* r, uint32_t addr) {
    asm volatile("ldmatrix.sync.aligned.m8n8.x4.shared.b16 {%0,%1,%2,%3}, [%4];"
                 : "=r"(r[0]), "=r"(r[1]), "=r"(r[2]), "=r"(r[3]) : "r"(addr));
}
// cp.async 16B (base ISA, sm_80+).
__device__ __forceinline__ void cpasync16(uint32_t saddr, const void* gptr) {
    asm volatile("cp.async.ca.shared.global [%0], [%1], 16;"
                 :: "r"(saddr), "l"(gptr) : "memory");
}
#define CP_COMMIT() asm volatile("cp.async.commit_group;" ::: "memory")
#define CP_WAIT1()  asm volatile("cp.async.wait_group 1;" ::: "memory")

// Packed fp32x2 FMA (PTX ISA sm_100+, base target).
typedef unsigned long long u64;
__device__ __forceinline__ u64 pk2(float x, float y) {
    u64 r; asm("mov.b64 %0, {%1, %2};" : "=l"(r) : "f"(x), "f"(y)); return r;
}
__device__ __forceinline__ void upk2(u64 v, float& x, float& y) {
    asm("mov.b64 {%0, %1}, %2;" : "=f"(x), "=f"(y) : "l"(v));
}
__device__ __forceinline__ u64 fma2_(u64 a, u64 b, u64 c) {
    u64 d; asm("fma.rn.f32x2 %0, %1, %2, %3;" : "=l"(d) : "l"(a), "l"(b), "l"(c));
    return d;
}

// ---------------------------------------------------------------------------
// k_cvtw: one-shot fp32 -> fp16 conversion of the three GEMM weight matrices.
// ---------------------------------------------------------------------------
__global__ __launch_bounds__(256) void k_cvtw(const float* __restrict__ Wf,
                                              const float* __restrict__ Wd,
                                              const float* __restrict__ Wi) {
    int i = blockIdx.x * 256 + threadIdx.x;
    const float4* src; __half* dst; int j;
    if (i < 16384)       { src = (const float4*)Wf; dst = g_Wfh; j = i; }
    else if (i < 32768)  { src = (const float4*)Wd; dst = g_Wdh; j = i - 16384; }
    else                 { src = (const float4*)Wi; dst = g_Wih; j = i - 32768; }
    float4 v = src[j];
    uint2 o; o.x = pack2(v.x, v.y); o.y = pack2(v.z, v.w);
    *(uint2*)(dst + j * 4) = o;
}

// ---------------------------------------------------------------------------
// k_init_hmma: g_h0h = leaky(inp @ W_init^T + b). Emits g_inph as side product.
// fp16 HMMA + ldmatrix fragments, CTA 128x64, 8 warps (4M x 2N), dbl-buffered.
// (R13 version — the 64-row retile of R15 regressed and is reverted.)
// ---------------------------------------------------------------------------
__global__ __launch_bounds__(256, 2) void k_init_hmma(const float* __restrict__ A,
                                                      const float* __restrict__ bias) {
    __shared__ uint32_t As[2][128][20];
    __shared__ uint32_t Ws[2][64][20];
    __shared__ float sb[64];
    const int tid = threadIdx.x;
    const int l = tid & 31, w = tid >> 5;
    const int g = l >> 2, c = l & 3;
    const int wm = w >> 1, wn = w & 1;
    const int rowBase = blockIdx.x * 128;
    const int wr = tid >> 2, wq = tid & 3;

    if (tid < 64) sb[tid] = bias[tid];

    const uint32_t asB = (uint32_t)__cvta_generic_to_shared(&As[0][0][0]);
    const uint32_t wsB = (uint32_t)__cvta_generic_to_shared(&Ws[0][0][0]);
    uint32_t aAddr[2], bAddr[2];
    #pragma unroll
    for (int mt = 0; mt < 2; mt++) {
        int row = wm * 32 + mt * 16 + (l & 15);
        aAddr[mt] = asB + (row * 20 + ((l & 16) ? 4 : 0)) * 4;
    }
    #pragma unroll
    for (int p = 0; p < 2; p++) {
        int row = wn * 32 + p * 16 + (l & 7) + ((l & 16) ? 8 : 0);
        bAddr[p] = wsB + (row * 20 + ((l & 8) ? 4 : 0)) * 4;
    }

    float acc[2][4][4] = {};
    float4 ra[4]; uint4 rw;

    auto ldA = [&](int kc) {
        #pragma unroll
        for (int i = 0; i < 4; i++) {
            int s = tid + i * 256;
            int r = rowBase + (s >> 3); if (r >= R) r = R - 1;
            ra[i] = *(const float4*)(A + (size_t)r * 256 + kc + ((s & 7) << 2));
        }
    };
    auto ldW = [&](int kc) {
        if (wr < 64) rw = *(const uint4*)(g_Wih + (size_t)wr * 256 + kc + wq * 8);
    };
    auto stAW = [&](int buf, int kc) {
        #pragma unroll
        for (int i = 0; i < 4; i++) {
            int s = tid + i * 256, r = s >> 3, c4 = s & 7;
            uint32_t p0 = pack2(ra[i].x, ra[i].y);
            uint32_t p1 = pack2(ra[i].z, ra[i].w);
            As[buf][r][c4 * 2]     = p0;
            As[buf][r][c4 * 2 + 1] = p1;
            int gr = rowBase + r; if (gr >= R) gr = R - 1;
            uint2 w2; w2.x = p0; w2.y = p1;
            *(uint2*)(g_inph + (size_t)gr * 256 + kc + (c4 << 2)) = w2;
        }
        if (wr < 64) {
            Ws[buf][wr][wq * 4 + 0] = rw.x; Ws[buf][wr][wq * 4 + 1] = rw.y;
            Ws[buf][wr][wq * 4 + 2] = rw.z; Ws[buf][wr][wq * 4 + 3] = rw.w;
        }
    };

    ldA(0); ldW(0); stAW(0, 0);
    __syncthreads();

    #pragma unroll 2
    for (int ch = 0; ch < 8; ch++) {
        const int cur = ch & 1;
        if (ch < 7) { ldA((ch + 1) * 32); ldW((ch + 1) * 32); }
        #pragma unroll
        for (int ks = 0; ks < 2; ks++) {
            uint32_t af[2][4], bq[2][4];
            const uint32_t ko = cur * 10240 + ks * 32;
            const uint32_t kw = cur * 5120  + ks * 32;
            ldsm4(af[0], aAddr[0] + ko);
            ldsm4(af[1], aAddr[1] + ko);
            ldsm4(bq[0], bAddr[0] + kw);
            ldsm4(bq[1], bAddr[1] + kw);
            #pragma unroll
            for (int mt = 0; mt < 2; mt++)
                #pragma unroll
                for (int nt = 0; nt < 4; nt++)
                    mma_fp16(acc[mt][nt], af[mt], &bq[nt >> 1][(nt & 1) * 2]);
        }
        if (ch < 7) stAW(cur ^ 1, (ch + 1) * 32);
        __syncthreads();
    }

    #pragma unroll
    for (int mt = 0; mt < 2; mt++) {
        int r0 = rowBase + wm * 32 + mt * 16 + g;
        #pragma unroll
        for (int nt = 0; nt < 4; nt++) {
            int col = wn * 32 + nt * 8 + c * 2;
            float b0 = sb[col], b1 = sb[col + 1];
            if (r0 < R)
                *(__half2*)(g_h0h + (size_t)r0 * 64 + col) =
                    __floats2half2_rn(leaky(acc[mt][nt][0] + b0), leaky(acc[mt][nt][1] + b1));
            if (r0 + 8 < R)
                *(__half2*)(g_h0h + (size_t)(r0 + 8) * 64 + col) =
                    __floats2half2_rn(leaky(acc[mt][nt][2] + b0), leaky(acc[mt][nt][3] + b1));
        }
    }
}

// ---------------------------------------------------------------------------
// k_geom: t1_mean (64) and t2_mean (128) per row; leaky per-k before mean.
// (R13 version — t2_mean to its own buffer; direct-x2 write reverted.)
// ---------------------------------------------------------------------------
__global__ __launch_bounds__(256) void k_geom(const float* __restrict__ G,
                                              const float* __restrict__ Wl1,
                                              const float* __restrict__ bl1,
                                              const float* __restrict__ Wl2,
                                              const float* __restrict__ bl2) {
    __shared__ float sg[64][64];
    __shared__ float sW[192][4];
    __shared__ float sb[192];
    const int tid = threadIdx.x;
    const int rowBase = blockIdx.x * 64;

    for (int t = tid; t < 1024; t += 256) {
        int r = t >> 4, c = t & 15;
        *(float4*)&sg[r][c * 4] = *(const float4*)(G + (size_t)(rowBase + r) * 64 + c * 4);
    }
    if (tid < 64) {
        #pragma unroll
        for (int j = 0; j < 4; j++) sW[tid][j] = Wl1[tid * 4 + j];
        sb[tid] = bl1[tid];
    } else if (tid < 192) {
        int o = tid - 64;
        #pragma unroll
        for (int j = 0; j < 4; j++) sW[tid][j] = Wl2[o * 4 + j];
        sb[tid] = bl2[o];
    }
    __syncthreads();

    const u64 C55 = pk2(0.55f, 0.55f);
    const u64 C45 = pk2(0.45f, 0.45f);

    for (int it = tid; it < 64 * 24; it += 256) {
        int row = it / 24;
        int ob  = (it - row * 24) * 8;
        u64 wp[4][4], bb2[4];
        #pragma unroll
        for (int o = 0; o < 4; o++) {
            #pragma unroll
            for (int j = 0; j < 4; j++)
                wp[j][o] = pk2(sW[ob + 2 * o][j], sW[ob + 2 * o + 1][j]);
            bb2[o] = pk2(sb[ob + 2 * o], sb[ob + 2 * o + 1]);
        }
        u64 acc2[4] = {0ull, 0ull, 0ull, 0ull};
        #pragma unroll
        for (int k = 0; k < 16; k++) {
            float4 gv = *(const float4*)&sg[row][k * 4];
            u64 gx = pk2(gv.x, gv.x), gy = pk2(gv.y, gv.y);
            u64 gz = pk2(gv.z, gv.z), gw = pk2(gv.w, gv.w);
            #pragma unroll
            for (int o = 0; o < 4; o++) {
                u64 d2 = fma2_(gx, wp[0][o], fma2_(gy, wp[1][o],
                         fma2_(gz, wp[2][o], fma2_(gw, wp[3][o], bb2[o]))));
                u64 a2 = d2 & 0x7FFFFFFF7FFFFFFFull;
                acc2[o] = fma2_(C55, d2, acc2[o]);
                acc2[o] = fma2_(C45, a2, acc2[o]);
            }
        }
        size_t gr = (size_t)(rowBase + row);
        #pragma unroll
        for (int o = 0; o < 4; o++) {
            float v0, v1; upk2(acc2[o], v0, v1);
            __half2 h = __floats2half2_rn(v0 * 0.0625f, v1 * 0.0625f);
            int oo = ob + o * 2;
            if (oo < 64) *(__half2*)(g_x1h  + gr * 128 + oo)      = h;
            else         *(__half2*)(g_t2mh + gr * 128 + oo - 64) = h;
        }
    }
}

// ---------------------------------------------------------------------------
// k_gather1: x1[r,64:128] = mean_k h0[batch(r), idx[r,k], :64]   (fp16 rows)
// TWO rows per warp (16-lane half-warps): per-point instruction count halves;
// 16 lanes x uint2 = the full 128B row, still perfectly coalesced.
// ---------------------------------------------------------------------------
__global__ __launch_bounds__(256) void k_gather1(const int* __restrict__ idx) {
    int row = blockIdx.x * 16 + (threadIdx.x >> 4);
    int hl  = threadIdx.x & 15;
    if (row >= R) return;
    int ipv = idx[(size_t)row * 16 + hl];
    const __half* base = g_h0h + (size_t)(row / Np) * Np * 64 + hl * 4;
    float a0 = 0.f, a1 = 0.f, a2 = 0.f, a3 = 0.f;
    #pragma unroll
    for (int k = 0; k < 16; k++) {
        int s = __shfl_sync(0xffffffffu, ipv, k, 16);
        uint2 v = *(const uint2*)(base + (size_t)s * 64);
        float2 f0 = __half22float2(*(__half2*)&v.x);
        float2 f1 = __half22float2(*(__half2*)&v.y);
        a0 += f0.x; a1 += f0.y; a2 += f1.x; a3 += f1.y;
    }
    __half2 p0 = __floats2half2_rn(a0 * 0.0625f, a1 * 0.0625f);
    __half2 p1 = __floats2half2_rn(a2 * 0.0625f, a3 * 0.0625f);
    uint2 o; o.x = *(uint32_t*)&p0; o.y = *(uint32_t*)&p1;
    *(uint2*)(g_x1h + (size_t)row * 128 + 64 + hl * 4) = o;
}

// ---------------------------------------------------------------------------
// k_gather2: x2[r] = [ t2m[r] | mean_k x1[batch(r), idx[r,k], :128] ] (fp16)
// TWO rows per warp; lane covers uint4 (16B) of each 256B neighbor row.
// ---------------------------------------------------------------------------
__global__ __launch_bounds__(256) void k_gather2(const int* __restrict__ idx) {
    int row = blockIdx.x * 16 + (threadIdx.x >> 4);
    int hl  = threadIdx.x & 15;
    if (row >= R) return;
    int ipv = idx[(size_t)row * 16 + hl];
    const __half* base = g_x1h + (size_t)(row / Np) * Np * 128 + hl * 8;
    float a[8] = {};
    #pragma unroll
    for (int k = 0; k < 16; k++) {
        int s = __shfl_sync(0xffffffffu, ipv, k, 16);
        uint4 v = *(const uint4*)(base + (size_t)s * 128);
        const uint32_t* vp = &v.x;
        #pragma unroll
        for (int j = 0; j < 4; j++) {
            float2 f = __half22float2(*(__half2*)&vp[j]);
            a[j * 2]     += f.x;
            a[j * 2 + 1] += f.y;
        }
    }
    uint4 t = *(const uint4*)(g_t2mh + (size_t)row * 128 + hl * 8);
    *(uint4*)(g_x2h + (size_t)row * 256 + hl * 8) = t;
    uint4 o;
    uint32_t* op = &o.x;
    #pragma unroll
    for (int j = 0; j < 4; j++) {
        __half2 p = __floats2half2_rn(a[j * 2] * 0.0625f, a[j * 2 + 1] * 0.0625f);
        op[j] = *(uint32_t*)&p;
    }
    *(uint4*)(g_x2h + (size_t)row * 256 + 128 + hl * 8) = o;
}

// ---------------------------------------------------------------------------
// k_final_hmma: out = leaky(x2 @ Wf^T + bf) + leaky(inp @ Wi^T + bi)
// fp16 HMMA, CTA 128x64, 256 thr, 2 CTAs/SM. Single 16-chunk mainloop
// (phase = ch>>3, fully unrolled) with 3-stage cp.async pipeline.
// Dual-phase register accumulators, ldmatrix fragments, single fused write.
// ---------------------------------------------------------------------------
__global__ __launch_bounds__(256, 2) void k_final_hmma(const __half* __restrict__ x2h,
                                                       const __half* __restrict__ inph,
                                                       const float* __restrict__ bf,
                                                       const float* __restrict__ bd,
                                                       float* __restrict__ out) {
    __shared__ uint32_t As[3][128][20];   // 3-stage, 10240B/stage
    __shared__ uint32_t Bs[3][64][20];    // 3-stage, 5120B/stage
    __shared__ float sbias[2][64];
    const int tid = threadIdx.x;
    const int l = tid & 31, w = tid >> 5;
    const int g = l >> 2, c = l & 3;
    const int wm = w >> 1, wn = w & 1;
    const int rowBase = (int)(blockIdx.x >> 2) * 128;
    const int colBase = (int)(blockIdx.x & 3) * 64;

    if (tid < 128) {
        int p = tid >> 6, j = tid & 63;
        sbias[p][j] = p ? bd[colBase + j] : bf[colBase + j];
    }

    const uint32_t asB = (uint32_t)__cvta_generic_to_shared(&As[0][0][0]);
    const uint32_t bsB = (uint32_t)__cvta_generic_to_shared(&Bs[0][0][0]);
    uint32_t aAddr[2], bAddr[2];
    #pragma unroll
    for (int mt = 0; mt < 2; mt++) {
        int row = wm * 32 + mt * 16 + (l & 15);
        aAddr[mt] = asB + (row * 20 + ((l & 16) ? 4 : 0)) * 4;
    }
    #pragma unroll
    for (int p = 0; p < 2; p++) {
        int row = wn * 32 + p * 16 + (l & 7) + ((l & 16) ? 8 : 0);
        bAddr[p] = bsB + (row * 20 + ((l & 8) ? 4 : 0)) * 4;
    }

    const int ar = tid >> 2, aq = tid & 3;
    int gr0 = rowBase + ar;      if (gr0 >= R) gr0 = R - 1;
    int gr1 = rowBase + ar + 64; if (gr1 >= R) gr1 = R - 1;

    auto issue = [&](int ch, int stg) {
        const int p = ch >> 3, kc = (ch & 7) << 5;
        const __half* A = p ? inph : x2h;
        const __half* W = p ? g_Wdh : g_Wfh;
        cpasync16(asB + stg * 10240 + ar * 80 + aq * 16,
                  A + (size_t)gr0 * 256 + kc + aq * 8);
        cpasync16(asB + stg * 10240 + (ar + 64) * 80 + aq * 16,
                  A + (size_t)gr1 * 256 + kc + aq * 8);
        cpasync16(bsB + stg * 5120 + ar * 80 + aq * 16,
                  W + (size_t)(colBase + ar) * 256 + kc + aq * 8);
    };

    float acc[2][8][4] = {};   // [phase][mt*4+nt][frag] — statically indexed

    issue(0, 0); CP_COMMIT();
    issue(1, 1); CP_COMMIT();

    #pragma unroll
    for (int ch = 0; ch < 16; ch++) {
        const int stg  = ch % 3;
        const int ph   = ch >> 3;
        CP_WAIT1();
        __syncthreads();
        #pragma unroll
        for (int ks = 0; ks < 2; ks++) {
            uint32_t af[2][4], bq[2][4];
            const uint32_t ko = stg * 10240 + ks * 32;
            const uint32_t kw = stg * 5120  + ks * 32;
            ldsm4(af[0], aAddr[0] + ko);
            ldsm4(af[1], aAddr[1] + ko);
            ldsm4(bq[0], bAddr[0] + kw);
            ldsm4(bq[1], bAddr[1] + kw);
            #pragma unroll
            for (int mt = 0; mt < 2; mt++)
                #pragma unroll
                for (int nt = 0; nt < 4; nt++)
                    mma_fp16(acc[ph][mt * 4 + nt], af[mt], &bq[nt >> 1][(nt & 1) * 2]);
        }
        __syncthreads();
        if (ch < 14) issue(ch + 2, (ch + 2) % 3);
        CP_COMMIT();
    }

    // Fused epilogue: single write of out.
    #pragma unroll
    for (int mt = 0; mt < 2; mt++) {
        int r0 = rowBase + wm * 32 + mt * 16 + g;
        #pragma unroll
        for (int nt = 0; nt < 4; nt++) {
            int lc = wn * 32 + nt * 8 + c * 2;
            int col = colBase + lc;
            float bf0 = sbias[0][lc], bf1 = sbias[0][lc + 1];
            float bd0 = sbias[1][lc], bd1 = sbias[1][lc + 1];
            const float* a0 = acc[0][mt * 4 + nt];
            const float* a1 = acc[1][mt * 4 + nt];
            if (r0 < R)
                *(float2*)(out + (size_t)r0 * 256 + col) = make_float2(
                    leaky(a0[0] + bf0) + leaky(a1[0] + bd0),
                    leaky(a0[1] + bf1) + leaky(a1[1] + bd1));
            if (r0 + 8 < R)
                *(float2*)(out + (size_t)(r0 + 8) * 256 + col) = make_float2(
                    leaky(a0[2] + bf0) + leaky(a1[2] + bd0),
                    leaky(a0[3] + bf1) + leaky(a1[3] + bd1));
        }
    }
}

// ---------------------------------------------------------------------------
extern "C" void kernel_launch(void* const* d_in, const int* in_sizes, int n_in,
                              void* d_out, int out_size) {
    const float* inp    = (const float*)d_in[0];   // [2,20000,256]
    const float* geom   = (const float*)d_in[1];   // [2,20000,16,4]
    const int*   idx    = (const int*)  d_in[2];   // [2,20000,16] int32
    const float* W_init = (const float*)d_in[3];
    const float* b_init = (const float*)d_in[4];
    const float* W_l1   = (const float*)d_in[5];
    const float* b_l1   = (const float*)d_in[6];
    const float* W_l2   = (const float*)d_in[7];
    const float* b_l2   = (const float*)d_in[8];
    const float* W_fin  = (const float*)d_in[9];
    const float* b_fin  = (const float*)d_in[10];
    const float* W_id   = (const float*)d_in[11];
    const float* b_id   = (const float*)d_in[12];
    float* out = (float*)d_out;

    __half* x2h;  cudaGetSymbolAddress((void**)&x2h,  g_x2h);
    __half* inph; cudaGetSymbolAddress((void**)&inph, g_inph);

    static cudaStream_t s2 = nullptr;
    static cudaEvent_t eFork = nullptr, eJoin = nullptr;
    if (!s2) {
        cudaStreamCreateWithFlags(&s2, cudaStreamNonBlocking);
        cudaEventCreateWithFlags(&eFork, cudaEventDisableTiming);
        cudaEventCreateWithFlags(&eJoin, cudaEventDisableTiming);
        cudaFuncSetAttribute(k_final_hmma,
                             cudaFuncAttributePreferredSharedMemoryCarveout, 100);
    }

    const int rowTiles = (R + 127) / 128;   // 313

    // Fork: k_geom is independent of the k_init chain until gather2.
    cudaEventRecord(eFork, 0);
    cudaStreamWaitEvent(s2, eFork, 0);
    k_geom<<<R / 64, 256, 0, s2>>>(geom, W_l1, b_l1, W_l2, b_l2);
    cudaEventRecord(eJoin, s2);

    // Main chain.
    k_cvtw      <<<144, 256>>>(W_fin, W_id, W_init);
    k_init_hmma <<<rowTiles, 256>>>(inp, b_init);
    k_gather1   <<<R / 16, 256>>>(idx);
    cudaStreamWaitEvent(0, eJoin, 0);
    k_gather2   <<<R / 16, 256>>>(idx);
    k_final_hmma<<<rowTiles * 4, 256>>>(x2h, inph, b_fin, b_id, out);
}

// round 17
// speedup vs baseline: 1.1844x; 1.0357x over previous
#include <cuda_runtime.h>
#include <cstdint>
#include <cuda_fp16.h>

// Problem constants (fixed by the reference).
constexpr int Bn = 2;
constexpr int Np = 20000;
constexpr int R  = Bn * Np;       // 40000 point rows

// Scratch (allocation-free rule: __device__ globals).
__device__ __half g_h0h [R * 64];    // leaky(inp @ W_init^T + b)      [R,64]
__device__ __half g_x1h [R * 128];   // [t1_mean | fn1_mean]           [R,128]
__device__ __half g_t2mh[R * 128];   // mean_k leaky(geom @ Wl2^T + b) [R,128]
__device__ __half g_x2h [R * 256];   // [t2_mean | fn2_mean]           [R,256]
__device__ __half g_inph[R * 256];   // fp16 copy of input (written by k_init)
__device__ __half g_Wfh [256 * 256]; // fp16 W_fin
__device__ __half g_Wdh [256 * 256]; // fp16 W_id
__device__ __half g_Wih [64 * 256];  // fp16 W_init

__device__ __forceinline__ float leaky(float x) { return x > 0.f ? x : 0.1f * x; }

__device__ __forceinline__ uint32_t pack2(float a, float b) {
    __half2 h = __floats2half2_rn(a, b);
    return *reinterpret_cast<uint32_t*>(&h);
}
// m16n8k16 row.col f32 <- f16*f16 + f32 (base ISA, sm_80+).
__device__ __forceinline__ void mma_fp16(float* c, const uint32_t* a, const uint32_t* b) {
    asm volatile(
        "mma.sync.aligned.m16n8k16.row.col.f32.f16.f16.f32 "
        "{%0,%1,%2,%3},{%4,%5,%6,%7},{%8,%9},{%0,%1,%2,%3};"
        : "+f"(c[0]), "+f"(c[1]), "+f"(c[2]), "+f"(c[3])
        : "r"(a[0]), "r"(a[1]), "r"(a[2]), "r"(a[3]), "r"(b[0]), "r"(b[1]));
}
// ldmatrix x4 (base ISA, sm_75+).
__device__ __forceinline__ void ldsm4(uint32_t* r, uint32_t addr) {
    asm volatile("ldmatrix.sync.aligned.m8n8.x4.shared.b16 {%0,%1,%2,%3}, [%4];"
                 : "=r"(r[0]), "=r"(r[1]), "=r"(r[2]), "=r"(r[3]) : "r"(addr));
}
// cp.async 16B (base ISA, sm_80+).
__device__ __forceinline__ void cpasync16(uint32_t saddr, const void* gptr) {
    asm volatile("cp.async.ca.shared.global [%0], [%1], 16;"
                 :: "r"(saddr), "l"(gptr) : "memory");
}
#define CP_COMMIT() asm volatile("cp.async.commit_group;" ::: "memory")
#define CP_WAIT1()  asm volatile("cp.async.wait_group 1;" ::: "memory")

// Packed fp32x2 FMA (PTX ISA sm_100+, base target).
typedef unsigned long long u64;
__device__ __forceinline__ u64 pk2(float x, float y) {
    u64 r; asm("mov.b64 %0, {%1, %2};" : "=l"(r) : "f"(x), "f"(y)); return r;
}
__device__ __forceinline__ void upk2(u64 v, float& x, float& y) {
    asm("mov.b64 {%0, %1}, %2;" : "=f"(x), "=f"(y) : "l"(v));
}
__device__ __forceinline__ u64 fma2_(u64 a, u64 b, u64 c) {
    u64 d; asm("fma.rn.f32x2 %0, %1, %2, %3;" : "=l"(d) : "l"(a), "l"(b), "l"(c));
    return d;
}

// ---------------------------------------------------------------------------
// k_cvtw: one-shot fp32 -> fp16 conversion of the three GEMM weight matrices.
// ---------------------------------------------------------------------------
__global__ __launch_bounds__(256) void k_cvtw(const float* __restrict__ Wf,
                                              const float* __restrict__ Wd,
                                              const float* __restrict__ Wi) {
    int i = blockIdx.x * 256 + threadIdx.x;
    const float4* src; __half* dst; int j;
    if (i < 16384)       { src = (const float4*)Wf; dst = g_Wfh; j = i; }
    else if (i < 32768)  { src = (const float4*)Wd; dst = g_Wdh; j = i - 16384; }
    else                 { src = (const float4*)Wi; dst = g_Wih; j = i - 32768; }
    float4 v = src[j];
    uint2 o; o.x = pack2(v.x, v.y); o.y = pack2(v.z, v.w);
    *(uint2*)(dst + j * 4) = o;
}

// ---------------------------------------------------------------------------
// k_init_hmma: g_h0h = leaky(inp @ W_init^T + b). Emits g_inph as side product.
// fp16 HMMA + ldmatrix fragments, CTA 128x64, 8 warps (4M x 2N), dbl-buffered.
// ---------------------------------------------------------------------------
__global__ __launch_bounds__(256, 2) void k_init_hmma(const float* __restrict__ A,
                                                      const float* __restrict__ bias) {
    __shared__ uint32_t As[2][128][20];
    __shared__ uint32_t Ws[2][64][20];
    __shared__ float sb[64];
    const int tid = threadIdx.x;
    const int l = tid & 31, w = tid >> 5;
    const int g = l >> 2, c = l & 3;
    const int wm = w >> 1, wn = w & 1;
    const int rowBase = blockIdx.x * 128;
    const int wr = tid >> 2, wq = tid & 3;

    if (tid < 64) sb[tid] = bias[tid];

    const uint32_t asB = (uint32_t)__cvta_generic_to_shared(&As[0][0][0]);
    const uint32_t wsB = (uint32_t)__cvta_generic_to_shared(&Ws[0][0][0]);
    uint32_t aAddr[2], bAddr[2];
    #pragma unroll
    for (int mt = 0; mt < 2; mt++) {
        int row = wm * 32 + mt * 16 + (l & 15);
        aAddr[mt] = asB + (row * 20 + ((l & 16) ? 4 : 0)) * 4;
    }
    #pragma unroll
    for (int p = 0; p < 2; p++) {
        int row = wn * 32 + p * 16 + (l & 7) + ((l & 16) ? 8 : 0);
        bAddr[p] = wsB + (row * 20 + ((l & 8) ? 4 : 0)) * 4;
    }

    float acc[2][4][4] = {};
    float4 ra[4]; uint4 rw;

    auto ldA = [&](int kc) {
        #pragma unroll
        for (int i = 0; i < 4; i++) {
            int s = tid + i * 256;
            int r = rowBase + (s >> 3); if (r >= R) r = R - 1;
            ra[i] = *(const float4*)(A + (size_t)r * 256 + kc + ((s & 7) << 2));
        }
    };
    auto ldW = [&](int kc) {
        if (wr < 64) rw = *(const uint4*)(g_Wih + (size_t)wr * 256 + kc + wq * 8);
    };
    auto stAW = [&](int buf, int kc) {
        #pragma unroll
        for (int i = 0; i < 4; i++) {
            int s = tid + i * 256, r = s >> 3, c4 = s & 7;
            uint32_t p0 = pack2(ra[i].x, ra[i].y);
            uint32_t p1 = pack2(ra[i].z, ra[i].w);
            As[buf][r][c4 * 2]     = p0;
            As[buf][r][c4 * 2 + 1] = p1;
            int gr = rowBase + r; if (gr >= R) gr = R - 1;
            uint2 w2; w2.x = p0; w2.y = p1;
            *(uint2*)(g_inph + (size_t)gr * 256 + kc + (c4 << 2)) = w2;
        }
        if (wr < 64) {
            Ws[buf][wr][wq * 4 + 0] = rw.x; Ws[buf][wr][wq * 4 + 1] = rw.y;
            Ws[buf][wr][wq * 4 + 2] = rw.z; Ws[buf][wr][wq * 4 + 3] = rw.w;
        }
    };

    ldA(0); ldW(0); stAW(0, 0);
    __syncthreads();

    #pragma unroll 2
    for (int ch = 0; ch < 8; ch++) {
        const int cur = ch & 1;
        if (ch < 7) { ldA((ch + 1) * 32); ldW((ch + 1) * 32); }
        #pragma unroll
        for (int ks = 0; ks < 2; ks++) {
            uint32_t af[2][4], bq[2][4];
            const uint32_t ko = cur * 10240 + ks * 32;
            const uint32_t kw = cur * 5120  + ks * 32;
            ldsm4(af[0], aAddr[0] + ko);
            ldsm4(af[1], aAddr[1] + ko);
            ldsm4(bq[0], bAddr[0] + kw);
            ldsm4(bq[1], bAddr[1] + kw);
            #pragma unroll
            for (int mt = 0; mt < 2; mt++)
                #pragma unroll
                for (int nt = 0; nt < 4; nt++)
                    mma_fp16(acc[mt][nt], af[mt], &bq[nt >> 1][(nt & 1) * 2]);
        }
        if (ch < 7) stAW(cur ^ 1, (ch + 1) * 32);
        __syncthreads();
    }

    #pragma unroll
    for (int mt = 0; mt < 2; mt++) {
        int r0 = rowBase + wm * 32 + mt * 16 + g;
        #pragma unroll
        for (int nt = 0; nt < 4; nt++) {
            int col = wn * 32 + nt * 8 + c * 2;
            float b0 = sb[col], b1 = sb[col + 1];
            if (r0 < R)
                *(__half2*)(g_h0h + (size_t)r0 * 64 + col) =
                    __floats2half2_rn(leaky(acc[mt][nt][0] + b0), leaky(acc[mt][nt][1] + b1));
            if (r0 + 8 < R)
                *(__half2*)(g_h0h + (size_t)(r0 + 8) * 64 + col) =
                    __floats2half2_rn(leaky(acc[mt][nt][2] + b0), leaky(acc[mt][nt][3] + b1));
        }
    }
}

// ---------------------------------------------------------------------------
// k_geom: t1_mean (64) and t2_mean (128) per row; leaky per-k before mean.
// ---------------------------------------------------------------------------
__global__ __launch_bounds__(256) void k_geom(const float* __restrict__ G,
                                              const float* __restrict__ Wl1,
                                              const float* __restrict__ bl1,
                                              const float* __restrict__ Wl2,
                                              const float* __restrict__ bl2) {
    __shared__ float sg[64][64];
    __shared__ float sW[192][4];
    __shared__ float sb[192];
    const int tid = threadIdx.x;
    const int rowBase = blockIdx.x * 64;

    for (int t = tid; t < 1024; t += 256) {
        int r = t >> 4, c = t & 15;
        *(float4*)&sg[r][c * 4] = *(const float4*)(G + (size_t)(rowBase + r) * 64 + c * 4);
    }
    if (tid < 64) {
        #pragma unroll
        for (int j = 0; j < 4; j++) sW[tid][j] = Wl1[tid * 4 + j];
        sb[tid] = bl1[tid];
    } else if (tid < 192) {
        int o = tid - 64;
        #pragma unroll
        for (int j = 0; j < 4; j++) sW[tid][j] = Wl2[o * 4 + j];
        sb[tid] = bl2[o];
    }
    __syncthreads();

    const u64 C55 = pk2(0.55f, 0.55f);
    const u64 C45 = pk2(0.45f, 0.45f);

    for (int it = tid; it < 64 * 24; it += 256) {
        int row = it / 24;
        int ob  = (it - row * 24) * 8;
        u64 wp[4][4], bb2[4];
        #pragma unroll
        for (int o = 0; o < 4; o++) {
            #pragma unroll
            for (int j = 0; j < 4; j++)
                wp[j][o] = pk2(sW[ob + 2 * o][j], sW[ob + 2 * o + 1][j]);
            bb2[o] = pk2(sb[ob + 2 * o], sb[ob + 2 * o + 1]);
        }
        u64 acc2[4] = {0ull, 0ull, 0ull, 0ull};
        #pragma unroll
        for (int k = 0; k < 16; k++) {
            float4 gv = *(const float4*)&sg[row][k * 4];
            u64 gx = pk2(gv.x, gv.x), gy = pk2(gv.y, gv.y);
            u64 gz = pk2(gv.z, gv.z), gw = pk2(gv.w, gv.w);
            #pragma unroll
            for (int o = 0; o < 4; o++) {
                u64 d2 = fma2_(gx, wp[0][o], fma2_(gy, wp[1][o],
                         fma2_(gz, wp[2][o], fma2_(gw, wp[3][o], bb2[o]))));
                u64 a2 = d2 & 0x7FFFFFFF7FFFFFFFull;
                acc2[o] = fma2_(C55, d2, acc2[o]);
                acc2[o] = fma2_(C45, a2, acc2[o]);
            }
        }
        size_t gr = (size_t)(rowBase + row);
        #pragma unroll
        for (int o = 0; o < 4; o++) {
            float v0, v1; upk2(acc2[o], v0, v1);
            __half2 h = __floats2half2_rn(v0 * 0.0625f, v1 * 0.0625f);
            int oo = ob + o * 2;
            if (oo < 64) *(__half2*)(g_x1h  + gr * 128 + oo)      = h;
            else         *(__half2*)(g_t2mh + gr * 128 + oo - 64) = h;
        }
    }
}

// ---------------------------------------------------------------------------
// k_gather1: x1[r,64:128] = mean_k h0[batch(r), idx[r,k], :64]   (fp16 rows)
// Two rows per warp (16-lane half-warps).
// ---------------------------------------------------------------------------
__global__ __launch_bounds__(256) void k_gather1(const int* __restrict__ idx) {
    int row = blockIdx.x * 16 + (threadIdx.x >> 4);
    int hl  = threadIdx.x & 15;
    if (row >= R) return;
    int ipv = idx[(size_t)row * 16 + hl];
    const __half* base = g_h0h + (size_t)(row / Np) * Np * 64 + hl * 4;
    float a0 = 0.f, a1 = 0.f, a2 = 0.f, a3 = 0.f;
    #pragma unroll
    for (int k = 0; k < 16; k++) {
        int s = __shfl_sync(0xffffffffu, ipv, k, 16);
        uint2 v = *(const uint2*)(base + (size_t)s * 64);
        float2 f0 = __half22float2(*(__half2*)&v.x);
        float2 f1 = __half22float2(*(__half2*)&v.y);
        a0 += f0.x; a1 += f0.y; a2 += f1.x; a3 += f1.y;
    }
    __half2 p0 = __floats2half2_rn(a0 * 0.0625f, a1 * 0.0625f);
    __half2 p1 = __floats2half2_rn(a2 * 0.0625f, a3 * 0.0625f);
    uint2 o; o.x = *(uint32_t*)&p0; o.y = *(uint32_t*)&p1;
    *(uint2*)(g_x1h + (size_t)row * 128 + 64 + hl * 4) = o;
}

// ---------------------------------------------------------------------------
// k_gather2: x2[r] = [ t2m[r] | mean_k x1[batch(r), idx[r,k], :128] ] (fp16)
// Two rows per warp; lane covers uint4 (16B) of each 256B neighbor row.
// ---------------------------------------------------------------------------
__global__ __launch_bounds__(256) void k_gather2(const int* __restrict__ idx) {
    int row = blockIdx.x * 16 + (threadIdx.x >> 4);
    int hl  = threadIdx.x & 15;
    if (row >= R) return;
    int ipv = idx[(size_t)row * 16 + hl];
    const __half* base = g_x1h + (size_t)(row / Np) * Np * 128 + hl * 8;
    float a[8] = {};
    #pragma unroll
    for (int k = 0; k < 16; k++) {
        int s = __shfl_sync(0xffffffffu, ipv, k, 16);
        uint4 v = *(const uint4*)(base + (size_t)s * 128);
        const uint32_t* vp = &v.x;
        #pragma unroll
        for (int j = 0; j < 4; j++) {
            float2 f = __half22float2(*(__half2*)&vp[j]);
            a[j * 2]     += f.x;
            a[j * 2 + 1] += f.y;
        }
    }
    uint4 t = *(const uint4*)(g_t2mh + (size_t)row * 128 + hl * 8);
    *(uint4*)(g_x2h + (size_t)row * 256 + hl * 8) = t;
    uint4 o;
    uint32_t* op = &o.x;
    #pragma unroll
    for (int j = 0; j < 4; j++) {
        __half2 p = __floats2half2_rn(a[j * 2] * 0.0625f, a[j * 2 + 1] * 0.0625f);
        op[j] = *(uint32_t*)&p;
    }
    *(uint4*)(g_x2h + (size_t)row * 256 + 128 + hl * 8) = o;
}

// ---------------------------------------------------------------------------
// k_final_hmma: out = leaky(x2 @ Wf^T + bf) + leaky(inp @ Wi^T + bi)
// fp16 HMMA, CTA 128x64, 256 thr, 2 CTAs/SM, 3-stage cp.async pipeline.
// ONE barrier per chunk (was two): sync(ch) already orders all warps past
// compute(ch-1) — the last reader of stage (ch+2)%3 — so the issue into that
// stage is hoisted directly after the barrier, ahead of compute(ch).
// ---------------------------------------------------------------------------
__global__ __launch_bounds__(256, 2) void k_final_hmma(const __half* __restrict__ x2h,
                                                       const __half* __restrict__ inph,
                                                       const float* __restrict__ bf,
                                                       const float* __restrict__ bd,
                                                       float* __restrict__ out) {
    __shared__ uint32_t As[3][128][20];   // 3-stage, 10240B/stage
    __shared__ uint32_t Bs[3][64][20];    // 3-stage, 5120B/stage
    __shared__ float sbias[2][64];
    const int tid = threadIdx.x;
    const int l = tid & 31, w = tid >> 5;
    const int g = l >> 2, c = l & 3;
    const int wm = w >> 1, wn = w & 1;
    const int rowBase = (int)(blockIdx.x >> 2) * 128;
    const int colBase = (int)(blockIdx.x & 3) * 64;

    if (tid < 128) {
        int p = tid >> 6, j = tid & 63;
        sbias[p][j] = p ? bd[colBase + j] : bf[colBase + j];
    }

    const uint32_t asB = (uint32_t)__cvta_generic_to_shared(&As[0][0][0]);
    const uint32_t bsB = (uint32_t)__cvta_generic_to_shared(&Bs[0][0][0]);
    uint32_t aAddr[2], bAddr[2];
    #pragma unroll
    for (int mt = 0; mt < 2; mt++) {
        int row = wm * 32 + mt * 16 + (l & 15);
        aAddr[mt] = asB + (row * 20 + ((l & 16) ? 4 : 0)) * 4;
    }
    #pragma unroll
    for (int p = 0; p < 2; p++) {
        int row = wn * 32 + p * 16 + (l & 7) + ((l & 16) ? 8 : 0);
        bAddr[p] = bsB + (row * 20 + ((l & 8) ? 4 : 0)) * 4;
    }

    const int ar = tid >> 2, aq = tid & 3;
    int gr0 = rowBase + ar;      if (gr0 >= R) gr0 = R - 1;
    int gr1 = rowBase + ar + 64; if (gr1 >= R) gr1 = R - 1;

    auto issue = [&](int ch, int stg) {
        const int p = ch >> 3, kc = (ch & 7) << 5;
        const __half* A = p ? inph : x2h;
        const __half* W = p ? g_Wdh : g_Wfh;
        cpasync16(asB + stg * 10240 + ar * 80 + aq * 16,
                  A + (size_t)gr0 * 256 + kc + aq * 8);
        cpasync16(asB + stg * 10240 + (ar + 64) * 80 + aq * 16,
                  A + (size_t)gr1 * 256 + kc + aq * 8);
        cpasync16(bsB + stg * 5120 + ar * 80 + aq * 16,
                  W + (size_t)(colBase + ar) * 256 + kc + aq * 8);
    };

    float acc[2][8][4] = {};   // [phase][mt*4+nt][frag] — statically indexed

    issue(0, 0); CP_COMMIT();
    issue(1, 1); CP_COMMIT();

    #pragma unroll
    for (int ch = 0; ch < 16; ch++) {
        const int stg  = ch % 3;
        const int ph   = ch >> 3;
        CP_WAIT1();                 // chunk ch resident (own groups)
        __syncthreads();            // publish + all warps past compute(ch-1)
        if (ch < 14) issue(ch + 2, (ch + 2) % 3);   // earliest safe point
        CP_COMMIT();                // empty group when ch >= 14 (legal)
        #pragma unroll
        for (int ks = 0; ks < 2; ks++) {
            uint32_t af[2][4], bq[2][4];
            const uint32_t ko = stg * 10240 + ks * 32;
            const uint32_t kw = stg * 5120  + ks * 32;
            ldsm4(af[0], aAddr[0] + ko);
            ldsm4(af[1], aAddr[1] + ko);
            ldsm4(bq[0], bAddr[0] + kw);
            ldsm4(bq[1], bAddr[1] + kw);
            #pragma unroll
            for (int mt = 0; mt < 2; mt++)
                #pragma unroll
                for (int nt = 0; nt < 4; nt++)
                    mma_fp16(acc[ph][mt * 4 + nt], af[mt], &bq[nt >> 1][(nt & 1) * 2]);
        }
    }

    // Fused epilogue: single write of out.
    #pragma unroll
    for (int mt = 0; mt < 2; mt++) {
        int r0 = rowBase + wm * 32 + mt * 16 + g;
        #pragma unroll
        for (int nt = 0; nt < 4; nt++) {
            int lc = wn * 32 + nt * 8 + c * 2;
            int col = colBase + lc;
            float bf0 = sbias[0][lc], bf1 = sbias[0][lc + 1];
            float bd0 = sbias[1][lc], bd1 = sbias[1][lc + 1];
            const float* a0 = acc[0][mt * 4 + nt];
            const float* a1 = acc[1][mt * 4 + nt];
            if (r0 < R)
                *(float2*)(out + (size_t)r0 * 256 + col) = make_float2(
                    leaky(a0[0] + bf0) + leaky(a1[0] + bd0),
                    leaky(a0[1] + bf1) + leaky(a1[1] + bd1));
            if (r0 + 8 < R)
                *(float2*)(out + (size_t)(r0 + 8) * 256 + col) = make_float2(
                    leaky(a0[2] + bf0) + leaky(a1[2] + bd0),
                    leaky(a0[3] + bf1) + leaky(a1[3] + bd1));
        }
    }
}

// ---------------------------------------------------------------------------
extern "C" void kernel_launch(void* const* d_in, const int* in_sizes, int n_in,
                              void* d_out, int out_size) {
    const float* inp    = (const float*)d_in[0];   // [2,20000,256]
    const float* geom   = (const float*)d_in[1];   // [2,20000,16,4]
    const int*   idx    = (const int*)  d_in[2];   // [2,20000,16] int32
    const float* W_init = (const float*)d_in[3];
    const float* b_init = (const float*)d_in[4];
    const float* W_l1   = (const float*)d_in[5];
    const float* b_l1   = (const float*)d_in[6];
    const float* W_l2   = (const float*)d_in[7];
    const float* b_l2   = (const float*)d_in[8];
    const float* W_fin  = (const float*)d_in[9];
    const float* b_fin  = (const float*)d_in[10];
    const float* W_id   = (const float*)d_in[11];
    const float* b_id   = (const float*)d_in[12];
    float* out = (float*)d_out;

    __half* x2h;  cudaGetSymbolAddress((void**)&x2h,  g_x2h);
    __half* inph; cudaGetSymbolAddress((void**)&inph, g_inph);

    static cudaStream_t s2 = nullptr;
    static cudaEvent_t eFork = nullptr, eJoin = nullptr;
    if (!s2) {
        cudaStreamCreateWithFlags(&s2, cudaStreamNonBlocking);
        cudaEventCreateWithFlags(&eFork, cudaEventDisableTiming);
        cudaEventCreateWithFlags(&eJoin, cudaEventDisableTiming);
        cudaFuncSetAttribute(k_final_hmma,
                             cudaFuncAttributePreferredSharedMemoryCarveout, 100);
    }

    const int rowTiles = (R + 127) / 128;   // 313

    // Fork: k_geom is independent of the k_init chain until gather2.
    cudaEventRecord(eFork, 0);
    cudaStreamWaitEvent(s2, eFork, 0);
    k_geom<<<R / 64, 256, 0, s2>>>(geom, W_l1, b_l1, W_l2, b_l2);
    cudaEventRecord(eJoin, s2);

    // Main chain.
    k_cvtw      <<<144, 256>>>(W_fin, W_id, W_init);
    k_init_hmma <<<rowTiles, 256>>>(inp, b_init);
    k_gather1   <<<R / 16, 256>>>(idx);
    cudaStreamWaitEvent(0, eJoin, 0);
    k_gather2   <<<R / 16, 256>>>(idx);
    k_final_hmma<<<rowTiles * 4, 256>>>(x2h, inph, b_fin, b_id, out);
}